// round 13
// baseline (speedup 1.0000x reference)
#include <cuda_runtime.h>
#include <cuda_bf16.h>
#include <math.h>
#include <cstdint>

// Problem constants
#define BB 4
#define TT 2048
#define EE 256
#define HH 8
#define HD 32
#define FEE 4
#define LL 4
#define MROWS (BB*TT)          // 8192
#define EPS 1e-5f

// ---------------------------------------------------------------------------
// Scratch (device globals; no runtime allocation allowed)
// ---------------------------------------------------------------------------
__device__ float g_x   [MROWS * EE];          // residual stream (full fp32)
__device__ float g_qkv [MROWS * 3 * EE];
__device__ float g_attn[MROWS * EE];
__device__ float g_ffh [MROWS * FEE * EE];
// transposed weights [N, K] row-major, per layer (tf32-rounded)
__device__ float g_qkvw_t[LL * 3 * EE * EE];
__device__ float g_outw_t[LL * EE * EE];
__device__ float g_ff1w_t[LL * FEE * EE * EE];
__device__ float g_ff2w_t[LL * FEE * EE * EE];

// ---------------------------------------------------------------------------
// PTX helpers (sm_80-era only; target is plain sm_103 — no tcgen05!)
// ---------------------------------------------------------------------------
__device__ __forceinline__ uint32_t smem_u32(const void* p) {
    uint32_t a;
    asm("{ .reg .u64 t; cvta.to.shared.u64 t, %1; cvt.u32.u64 %0, t; }" : "=r"(a) : "l"(p));
    return a;
}

__device__ __forceinline__ float tf32_rn(float x) {
    uint32_t u;
    asm("cvt.rna.tf32.f32 %0, %1;" : "=r"(u) : "f"(x));
    return __uint_as_float(u);
}

#define CP_ASYNC16(dst, src) \
    asm volatile("cp.async.cg.shared.global [%0], [%1], 16;\n" :: "r"(dst), "l"(src))
#define CP_COMMIT() asm volatile("cp.async.commit_group;\n" ::)
#define CP_WAIT1() asm volatile("cp.async.wait_group 1;\n" ::)
#define CP_WAIT0() asm volatile("cp.async.wait_group 0;\n" ::)

#define LDSM_X4(r, addr) \
    asm volatile("ldmatrix.sync.aligned.m8n8.x4.shared.b16 {%0,%1,%2,%3}, [%4];" \
        : "=r"((r)[0]), "=r"((r)[1]), "=r"((r)[2]), "=r"((r)[3]) : "r"(addr))

__device__ __forceinline__ void mma_tf32(float c[4], const uint32_t a[4], const uint32_t b[2]) {
    asm volatile("mma.sync.aligned.m16n8k8.row.col.f32.tf32.tf32.f32 "
        "{%0,%1,%2,%3}, {%4,%5,%6,%7}, {%8,%9}, {%0,%1,%2,%3};"
        : "+f"(c[0]), "+f"(c[1]), "+f"(c[2]), "+f"(c[3])
        : "r"(a[0]), "r"(a[1]), "r"(a[2]), "r"(a[3]), "r"(b[0]), "r"(b[1]));
}

// ---------------------------------------------------------------------------
// Positional encoding (full precision; GEMM rounds A in-register)
// ---------------------------------------------------------------------------
__global__ void pe_kernel(const float* __restrict__ x, float* __restrict__ out) {
    int idx = blockIdx.x * blockDim.x + threadIdx.x;
    if (idx >= MROWS * EE) return;
    int e = idx & (EE - 1);
    int t = (idx / EE) & (TT - 1);
    int i = (e < 128) ? e : e - 128;
    float f = __expf(-((2.0f * (float)i) * (1.0f / (float)EE)) * 9.210340371976184f);
    float ang = (float)t * f;
    float pe = (e < 128) ? sinf(ang) : cosf(ang);
    out[idx] = x[idx] + pe;
}

// ---------------------------------------------------------------------------
// Merged weight transpose + tf32 RN: all 4 weights, all layers, one launch.
// Tile ids: [0,768) qkv | [768,1024) out | [1024,2048) ff1 | [2048,3072) ff2
// ---------------------------------------------------------------------------
__global__ void transpose_all_kernel(const float* __restrict__ qkv_w,
                                     const float* __restrict__ out_w,
                                     const float* __restrict__ ff1_w,
                                     const float* __restrict__ ff2_w,
                                     float* __restrict__ wq, float* __restrict__ wo,
                                     float* __restrict__ w1, float* __restrict__ w2) {
    __shared__ float tile[32][33];
    int id = blockIdx.x;
    const float* in; float* out; int K, N, ntiles;
    if (id < 768)        { in = qkv_w; out = wq; K = 256;  N = 768;  ntiles = 24; }
    else if (id < 1024)  { id -= 768;  in = out_w; out = wo; K = 256;  N = 256;  ntiles = 8; }
    else if (id < 2048)  { id -= 1024; in = ff1_w; out = w1; K = 256;  N = 1024; ntiles = 32; }
    else                 { id -= 2048; in = ff2_w; out = w2; K = 1024; N = 256;  ntiles = 8; }
    const int per_layer = ntiles * (K / 32);
    const int l = id / per_layer;
    const int r = id % per_layer;
    const int n0 = (r % ntiles) * 32;
    const int k0 = (r / ntiles) * 32;
    const size_t plane = (size_t)K * N;
    const float* ip = in + (size_t)l * plane;
    float* op = out + (size_t)l * plane;
    int tx = threadIdx.x, ty = threadIdx.y;
    #pragma unroll
    for (int i = 0; i < 32; i += 8)
        tile[ty + i][tx] = ip[(size_t)(k0 + ty + i) * N + n0 + tx];
    __syncthreads();
    #pragma unroll
    for (int i = 0; i < 32; i += 8)
        op[(size_t)(n0 + ty + i) * K + k0 + tx] = tf32_rn(tile[tx][ty + i]);
}

// ---------------------------------------------------------------------------
// tf32 mma.sync GEMM: C[M,N] = A[M,K] @ Bt[N,K]^T + bias
// A rounded in-register (RN); Bt pre-rounded. mode bit0=ReLU, bit1=round out.
// Block tile 128x128, BK=32, 8 warps (2m x 4n), 3-stage cp.async pipeline.
// ---------------------------------------------------------------------------
#define GSTAGE 32768           // A (16KB) + B (16KB) per stage
#define GSMEM_TOTAL (3 * GSTAGE)

__device__ __forceinline__ void gemm_load_stage(uint32_t sbase, const float* A, const float* Bt,
                                                int K, int bm, int bn, int kt, int tid) {
    uint32_t abuf = sbase + (uint32_t)(kt % 3) * GSTAGE;
    uint32_t bbuf = abuf + 16384;
    const float* ap = A + (size_t)bm * K + kt * 32;
    const float* bp = Bt + (size_t)bn * K + kt * 32;
    #pragma unroll
    for (int i = 0; i < 4; i++) {
        int f = tid + i * 256;
        int r = f >> 3;
        int cB = (f & 7) * 16;
        uint32_t off = (uint32_t)(r * 128 + cB);
        uint32_t sw = off ^ ((off >> 3) & 0x70);
        CP_ASYNC16(abuf + sw, ap + (size_t)r * K + (cB >> 2));
        CP_ASYNC16(bbuf + sw, bp + (size_t)r * K + (cB >> 2));
    }
    CP_COMMIT();
}

__global__ __launch_bounds__(256)
void gemm_tc_kernel(const float* __restrict__ A, const float* __restrict__ Bt,
                    const float* __restrict__ bias, float* __restrict__ C,
                    int N, int K, int mode) {
    extern __shared__ char smem[];
    uint32_t sbase = smem_u32(smem);
    const int tid = threadIdx.x;
    const int wid = tid >> 5;
    const int lane = tid & 31;
    const int warpM = wid & 1;
    const int warpN = wid >> 1;
    const int bn = blockIdx.x * 128;
    const int bm = blockIdx.y * 128;

    float acc[4][4][4];
    #pragma unroll
    for (int mt = 0; mt < 4; mt++)
        #pragma unroll
        for (int nt = 0; nt < 4; nt++)
            #pragma unroll
            for (int r = 0; r < 4; r++) acc[mt][nt][r] = 0.0f;

    const uint32_t mask = (uint32_t)(lane & 7) << 4;
    uint32_t arowb[4];
    #pragma unroll
    for (int mt = 0; mt < 4; mt++)
        arowb[mt] = (uint32_t)(warpM * 64 + (lane & 15) + mt * 16) * 128;
    const uint32_t achunk = (uint32_t)(lane >> 4) * 16;
    uint32_t browb[2];
    #pragma unroll
    for (int nh = 0; nh < 2; nh++)
        browb[nh] = (uint32_t)(warpN * 32 + nh * 16 + (lane & 7) + ((lane >> 4) << 3)) * 128;
    const uint32_t bchunk = (uint32_t)((lane >> 3) & 1) * 16;

    const int nk = K / 32;
    gemm_load_stage(sbase, A, Bt, K, bm, bn, 0, tid);
    gemm_load_stage(sbase, A, Bt, K, bm, bn, 1, tid);

    for (int kt = 0; kt < nk; kt++) {
        if (kt + 1 < nk) { CP_WAIT1(); } else { CP_WAIT0(); }
        __syncthreads();
        if (kt + 2 < nk) gemm_load_stage(sbase, A, Bt, K, bm, bn, kt + 2, tid);

        const uint32_t ab = sbase + (uint32_t)(kt % 3) * GSTAGE;
        const uint32_t bb = ab + 16384;

        #pragma unroll
        for (int ks = 0; ks < 4; ks++) {
            const uint32_t aco = ((uint32_t)(ks * 32) + achunk) ^ mask;
            const uint32_t bco = ((uint32_t)(ks * 32) + bchunk) ^ mask;

            uint32_t afr[4][4], bfr[2][4];
            #pragma unroll
            for (int mt = 0; mt < 4; mt++) LDSM_X4(afr[mt], ab + arowb[mt] + aco);
            #pragma unroll
            for (int nh = 0; nh < 2; nh++) LDSM_X4(bfr[nh], bb + browb[nh] + bco);

            // RN-round activations to tf32 (weights already pre-rounded)
            #pragma unroll
            for (int mt = 0; mt < 4; mt++)
                #pragma unroll
                for (int r = 0; r < 4; r++)
                    afr[mt][r] = __float_as_uint(tf32_rn(__uint_as_float(afr[mt][r])));

            #pragma unroll
            for (int mt = 0; mt < 4; mt++)
                #pragma unroll
                for (int nt = 0; nt < 4; nt++)
                    mma_tf32(acc[mt][nt], afr[mt], &bfr[nt >> 1][(nt & 1) * 2]);
        }
    }

    #pragma unroll
    for (int mt = 0; mt < 4; mt++) {
        const int row0 = bm + warpM * 64 + mt * 16 + (lane >> 2);
        #pragma unroll
        for (int nt = 0; nt < 4; nt++) {
            const int col = bn + warpN * 32 + nt * 8 + (lane & 3) * 2;
            const float2 bi = *(const float2*)&bias[col];
            float v0 = acc[mt][nt][0] + bi.x;
            float v1 = acc[mt][nt][1] + bi.y;
            float v2 = acc[mt][nt][2] + bi.x;
            float v3 = acc[mt][nt][3] + bi.y;
            if (mode & 1) {
                v0 = fmaxf(v0, 0.0f); v1 = fmaxf(v1, 0.0f);
                v2 = fmaxf(v2, 0.0f); v3 = fmaxf(v3, 0.0f);
            }
            if (mode & 2) {
                v0 = tf32_rn(v0); v1 = tf32_rn(v1);
                v2 = tf32_rn(v2); v3 = tf32_rn(v3);
            }
            float2 p0; p0.x = v0; p0.y = v1;
            float2 p1; p1.x = v2; p1.y = v3;
            *(float2*)&C[(size_t)row0 * N + col] = p0;
            *(float2*)&C[(size_t)(row0 + 8) * N + col] = p1;
        }
    }
}

// ---------------------------------------------------------------------------
// Fused GEMM (N=256) + bias + residual + LayerNorm:
//   out = LN(res + A @ Bt^T + bias) * g + beta   (full precision, single write)
// BM=64, BN=256, 8 warps (2m x 4n). A inputs are producer-rounded tf32.
// ---------------------------------------------------------------------------
#define LSTAGE 40960           // A (8KB) + B (32KB)
#define LSMEM_TOTAL (3 * LSTAGE)

__device__ __forceinline__ void gemmln_load_stage(uint32_t sbase, const float* A, const float* Bt,
                                                  int K, int bm, int kt, int tid) {
    uint32_t abuf = sbase + (uint32_t)(kt % 3) * LSTAGE;
    uint32_t bbuf = abuf + 8192;
    const float* ap = A + (size_t)bm * K + kt * 32;
    const float* bp = Bt + kt * 32;
    #pragma unroll
    for (int i = 0; i < 2; i++) {
        int f = tid + i * 256;
        int r = f >> 3;
        int cB = (f & 7) * 16;
        uint32_t off = (uint32_t)(r * 128 + cB);
        uint32_t sw = off ^ ((off >> 3) & 0x70);
        CP_ASYNC16(abuf + sw, ap + (size_t)r * K + (cB >> 2));
    }
    #pragma unroll
    for (int i = 0; i < 8; i++) {
        int f = tid + i * 256;
        int r = f >> 3;
        int cB = (f & 7) * 16;
        uint32_t off = (uint32_t)(r * 128 + cB);
        uint32_t sw = off ^ ((off >> 3) & 0x70);
        CP_ASYNC16(bbuf + sw, bp + (size_t)r * K + (cB >> 2));
    }
    CP_COMMIT();
}

__global__ __launch_bounds__(256)
void gemm_ln_kernel(const float* __restrict__ A, const float* __restrict__ Bt,
                    const float* __restrict__ bias, const float* __restrict__ res,
                    const float* __restrict__ g, const float* __restrict__ beta,
                    float* __restrict__ out, int K) {
    extern __shared__ char smem[];
    uint32_t sbase = smem_u32(smem);
    const int tid = threadIdx.x;
    const int wid = tid >> 5;
    const int lane = tid & 31;
    const int warpM = wid & 1;
    const int warpN = wid >> 1;
    const int bm = blockIdx.x * 64;

    float acc[2][8][4];
    #pragma unroll
    for (int mt = 0; mt < 2; mt++)
        #pragma unroll
        for (int nt = 0; nt < 8; nt++)
            #pragma unroll
            for (int r = 0; r < 4; r++) acc[mt][nt][r] = 0.0f;

    const uint32_t mask = (uint32_t)(lane & 7) << 4;
    uint32_t arowb[2];
    #pragma unroll
    for (int mt = 0; mt < 2; mt++)
        arowb[mt] = (uint32_t)(warpM * 32 + mt * 16 + (lane & 15)) * 128;
    const uint32_t achunk = (uint32_t)(lane >> 4) * 16;
    uint32_t browb[4];
    #pragma unroll
    for (int nh = 0; nh < 4; nh++)
        browb[nh] = (uint32_t)(warpN * 64 + nh * 16 + (lane & 7) + ((lane >> 4) << 3)) * 128;
    const uint32_t bchunk = (uint32_t)((lane >> 3) & 1) * 16;

    const int nk = K / 32;
    gemmln_load_stage(sbase, A, Bt, K, bm, 0, tid);
    gemmln_load_stage(sbase, A, Bt, K, bm, 1, tid);

    for (int kt = 0; kt < nk; kt++) {
        if (kt + 1 < nk) { CP_WAIT1(); } else { CP_WAIT0(); }
        __syncthreads();
        if (kt + 2 < nk) gemmln_load_stage(sbase, A, Bt, K, bm, kt + 2, tid);

        const uint32_t ab = sbase + (uint32_t)(kt % 3) * LSTAGE;
        const uint32_t bb = ab + 8192;

        #pragma unroll
        for (int ks = 0; ks < 4; ks++) {
            const uint32_t aco = ((uint32_t)(ks * 32) + achunk) ^ mask;
            const uint32_t bco = ((uint32_t)(ks * 32) + bchunk) ^ mask;

            uint32_t afr[2][4], bfr[4][4];
            #pragma unroll
            for (int mt = 0; mt < 2; mt++) LDSM_X4(afr[mt], ab + arowb[mt] + aco);
            #pragma unroll
            for (int nh = 0; nh < 4; nh++) LDSM_X4(bfr[nh], bb + browb[nh] + bco);

            #pragma unroll
            for (int mt = 0; mt < 2; mt++)
                #pragma unroll
                for (int nt = 0; nt < 8; nt++)
                    mma_tf32(acc[mt][nt], afr[mt], &bfr[nt >> 1][(nt & 1) * 2]);
        }
    }
    __syncthreads();   // smem free for reductions now

    float* redS = (float*)smem;           // [64][4]
    float* redQ = (float*)smem + 256;     // [64][4]

    const int rl = lane >> 2;
    const int cl = (lane & 3) * 2;
    float sum[2][2] = {{0,0},{0,0}}, sq[2][2] = {{0,0},{0,0}};

    #pragma unroll
    for (int mt = 0; mt < 2; mt++) {
        const int rlo = bm + warpM * 32 + mt * 16 + rl;
        #pragma unroll
        for (int nt = 0; nt < 8; nt++) {
            const int col = warpN * 64 + nt * 8 + cl;
            const float2 bi = *(const float2*)&bias[col];
            const float2 r0 = *(const float2*)&res[(size_t)rlo * EE + col];
            const float2 r1 = *(const float2*)&res[(size_t)(rlo + 8) * EE + col];
            float v0 = acc[mt][nt][0] + bi.x + r0.x;
            float v1 = acc[mt][nt][1] + bi.y + r0.y;
            float v2 = acc[mt][nt][2] + bi.x + r1.x;
            float v3 = acc[mt][nt][3] + bi.y + r1.y;
            acc[mt][nt][0] = v0; acc[mt][nt][1] = v1;
            acc[mt][nt][2] = v2; acc[mt][nt][3] = v3;
            sum[mt][0] += v0 + v1;     sum[mt][1] += v2 + v3;
            sq[mt][0]  += v0*v0 + v1*v1; sq[mt][1] += v2*v2 + v3*v3;
        }
    }
    #pragma unroll
    for (int mt = 0; mt < 2; mt++)
        #pragma unroll
        for (int hh = 0; hh < 2; hh++) {
            sum[mt][hh] += __shfl_xor_sync(0xffffffffu, sum[mt][hh], 1);
            sum[mt][hh] += __shfl_xor_sync(0xffffffffu, sum[mt][hh], 2);
            sq[mt][hh]  += __shfl_xor_sync(0xffffffffu, sq[mt][hh], 1);
            sq[mt][hh]  += __shfl_xor_sync(0xffffffffu, sq[mt][hh], 2);
        }
    if ((lane & 3) == 0) {
        #pragma unroll
        for (int mt = 0; mt < 2; mt++) {
            int rloc = warpM * 32 + mt * 16 + rl;
            redS[rloc * 4 + warpN] = sum[mt][0];
            redQ[rloc * 4 + warpN] = sq[mt][0];
            redS[(rloc + 8) * 4 + warpN] = sum[mt][1];
            redQ[(rloc + 8) * 4 + warpN] = sq[mt][1];
        }
    }
    __syncthreads();

    #pragma unroll
    for (int mt = 0; mt < 2; mt++) {
        #pragma unroll
        for (int hh = 0; hh < 2; hh++) {
            const int rloc = warpM * 32 + mt * 16 + rl + hh * 8;
            float ts = redS[rloc * 4 + 0] + redS[rloc * 4 + 1]
                     + redS[rloc * 4 + 2] + redS[rloc * 4 + 3];
            float tq = redQ[rloc * 4 + 0] + redQ[rloc * 4 + 1]
                     + redQ[rloc * 4 + 2] + redQ[rloc * 4 + 3];
            const float mu = ts * (1.0f / (float)EE);
            const float var = tq * (1.0f / (float)EE) - mu * mu;
            const float inv = rsqrtf(var + EPS);
            const int row = bm + rloc;
            #pragma unroll
            for (int nt = 0; nt < 8; nt++) {
                const int col = warpN * 64 + nt * 8 + cl;
                const float2 gg = *(const float2*)&g[col];
                const float2 bb = *(const float2*)&beta[col];
                float v0 = acc[mt][nt][2 * hh + 0];
                float v1 = acc[mt][nt][2 * hh + 1];
                float2 o;
                o.x = (v0 - mu) * inv * gg.x + bb.x;
                o.y = (v1 - mu) * inv * gg.y + bb.y;
                *(float2*)&out[(size_t)row * EE + col] = o;
            }
        }
    }
}

// ---------------------------------------------------------------------------
// Tensor-core flash attention (tf32 mma.sync) with cp.async KV pipeline.
// Block = (b,h) x 128-query tile; 8 warps x 16 rows. KV tiles of 64 keys,
// 3-stage cp.async. qkv values are pre-rounded to tf32 by the QKV GEMM.
// Softmax in log2 domain (Q scaled by scale*log2e; exp2f).
// qkv layout: [B,T,H,3,HD] -> (b*T+t)*768 + h*96 + s*32 + d
// ---------------------------------------------------------------------------
#define AST_K 8192                      // 64 keys x 128B (swizzled)
#define AST_V 10240                     // 64 keys x 40 floats
#define ASTAGE (AST_K + AST_V)          // 18432
#define APOFF (3 * ASTAGE)              // 55296: P buffers
#define PWARP (16 * 68 * 4)             // 4352 bytes per warp
#define ASMEM_TOTAL (APOFF + 8 * PWARP) // 90112

__device__ __forceinline__ void attn_load_kv(uint32_t sbase, const float* kv0,
                                             int kt, int tid) {
    uint32_t kbuf = sbase + (uint32_t)(kt % 3) * ASTAGE;
    uint32_t vbuf = kbuf + AST_K;
    const float* src0 = kv0 + (size_t)(kt * 64) * 768;
    #pragma unroll
    for (int i = 0; i < 2; i++) {
        int f = tid + i * 256;           // 0..511
        int j = f >> 3;                  // key 0..63
        int c = f & 7;                   // 16B chunk
        const float* s = src0 + (size_t)j * 768 + 32 + c * 4;   // K slot
        uint32_t koff = (uint32_t)(j * 128 + c * 16);
        CP_ASYNC16(kbuf + (koff ^ ((koff >> 3) & 0x70)), s);
        CP_ASYNC16(vbuf + (uint32_t)(j * 160 + c * 16), s + 32); // V slot
    }
    CP_COMMIT();
}

__global__ __launch_bounds__(256)
void attn_tc_kernel(const float* __restrict__ qkv, float* __restrict__ out) {
    extern __shared__ char smem[];
    uint32_t sbase = smem_u32(smem);

    const int tid = threadIdx.x;
    const int wid = tid >> 5;
    const int lane = tid & 31;
    const int qt = blockIdx.x;               // 0..15 (128 queries each)
    const int bh = blockIdx.y;               // 0..31
    const int h = bh & (HH - 1);
    const int b = bh >> 3;

    // scale * log2(e): softmax computed in log2 domain
    const float scale = 0.2550348612890183f;

    // --- Q fragments (A, m16k8 x 4 ksteps), pre-scaled + tf32 RN rounded ---
    uint32_t qfr[4][4];
    {
        const int r_lo = qt * 128 + wid * 16 + (lane >> 2);
        const size_t base_lo = (size_t)(b * TT + r_lo) * 768 + h * 96;
        const size_t base_hi = base_lo + 8 * 768;
        #pragma unroll
        for (int ks = 0; ks < 4; ks++) {
            int c0 = ks * 8 + (lane & 3);
            qfr[ks][0] = __float_as_uint(tf32_rn(qkv[base_lo + c0] * scale));
            qfr[ks][1] = __float_as_uint(tf32_rn(qkv[base_hi + c0] * scale));
            qfr[ks][2] = __float_as_uint(tf32_rn(qkv[base_lo + c0 + 4] * scale));
            qfr[ks][3] = __float_as_uint(tf32_rn(qkv[base_hi + c0 + 4] * scale));
        }
    }

    float ofr[4][4];
    #pragma unroll
    for (int nd = 0; nd < 4; nd++)
        #pragma unroll
        for (int r = 0; r < 4; r++) ofr[nd][r] = 0.0f;
    float m_lo = -INFINITY, m_hi = -INFINITY, l_lo = 0.0f, l_hi = 0.0f;

    // K ldmatrix addressing (B fragments over 64 keys)
    const uint32_t mask = (uint32_t)(lane & 7) << 4;
    const uint32_t krow = (uint32_t)((lane & 7) + ((lane >> 4) << 3)) * 128;
    const uint32_t kchunk = (uint32_t)((lane >> 3) & 1) * 16;

    // P buffers
    float* Pw = (float*)(smem + APOFF + wid * PWARP);
    const uint32_t pldsm = sbase + APOFF + (uint32_t)(wid * PWARP)
                         + (uint32_t)((lane & 15) * 272) + ((uint32_t)(lane >> 4) << 4);

    const float* kv0 = qkv + (size_t)(b * TT) * 768 + h * 96;

    attn_load_kv(sbase, kv0, 0, tid);
    attn_load_kv(sbase, kv0, 1, tid);

    const int nk = TT / 64;
    for (int kt = 0; kt < nk; kt++) {
        if (kt + 1 < nk) { CP_WAIT1(); } else { CP_WAIT0(); }
        __syncthreads();
        if (kt + 2 < nk) attn_load_kv(sbase, kv0, kt + 2, tid);

        const uint32_t kb = sbase + (uint32_t)(kt % 3) * ASTAGE;
        const uint32_t* Vsu = (const uint32_t*)(smem + (kt % 3) * ASTAGE + AST_K);

        // --- S = Q K^T ---
        float sfr[8][4];
        #pragma unroll
        for (int nt = 0; nt < 8; nt++)
            #pragma unroll
            for (int r = 0; r < 4; r++) sfr[nt][r] = 0.0f;

        #pragma unroll
        for (int ks = 0; ks < 4; ks++) {
            const uint32_t co = ((uint32_t)(ks * 32) + kchunk) ^ mask;
            uint32_t kfr[4][4];
            #pragma unroll
            for (int gI = 0; gI < 4; gI++)
                LDSM_X4(kfr[gI], kb + (uint32_t)(gI * 16 * 128) + krow + co);
            #pragma unroll
            for (int nt = 0; nt < 8; nt++)
                mma_tf32(sfr[nt], qfr[ks], &kfr[nt >> 1][(nt & 1) * 2]);
        }

        // --- online softmax (log2 domain) ---
        float mx_lo = sfr[0][0], mx_hi = sfr[0][2];
        #pragma unroll
        for (int nt = 0; nt < 8; nt++) {
            mx_lo = fmaxf(mx_lo, fmaxf(sfr[nt][0], sfr[nt][1]));
            mx_hi = fmaxf(mx_hi, fmaxf(sfr[nt][2], sfr[nt][3]));
        }
        mx_lo = fmaxf(mx_lo, __shfl_xor_sync(0xffffffffu, mx_lo, 1));
        mx_lo = fmaxf(mx_lo, __shfl_xor_sync(0xffffffffu, mx_lo, 2));
        mx_hi = fmaxf(mx_hi, __shfl_xor_sync(0xffffffffu, mx_hi, 1));
        mx_hi = fmaxf(mx_hi, __shfl_xor_sync(0xffffffffu, mx_hi, 2));

        const float nm_lo = fmaxf(m_lo, mx_lo);
        const float nm_hi = fmaxf(m_hi, mx_hi);
        const float corr_lo = exp2f(m_lo - nm_lo);   // 2^-inf = 0 first tile
        const float corr_hi = exp2f(m_hi - nm_hi);
        m_lo = nm_lo; m_hi = nm_hi;

        float ps_lo = 0.0f, ps_hi = 0.0f;
        {
            const int rl = (lane >> 2);
            const int cb = 2 * (lane & 3);
            float* prow_lo = Pw + rl * 68 + cb;
            float* prow_hi = Pw + (rl + 8) * 68 + cb;
            #pragma unroll
            for (int nt = 0; nt < 8; nt++) {
                float p0 = exp2f(sfr[nt][0] - m_lo);
                float p1 = exp2f(sfr[nt][1] - m_lo);
                float p2 = exp2f(sfr[nt][2] - m_hi);
                float p3 = exp2f(sfr[nt][3] - m_hi);
                ps_lo += p0 + p1;
                ps_hi += p2 + p3;
                float2 w0; w0.x = tf32_rn(p0); w0.y = tf32_rn(p1);
                float2 w1; w1.x = tf32_rn(p2); w1.y = tf32_rn(p3);
                *(float2*)(prow_lo + nt * 8) = w0;
                *(float2*)(prow_hi + nt * 8) = w1;
            }
        }
        l_lo = l_lo * corr_lo + ps_lo;
        l_hi = l_hi * corr_hi + ps_hi;
        #pragma unroll
        for (int nd = 0; nd < 4; nd++) {
            ofr[nd][0] *= corr_lo; ofr[nd][1] *= corr_lo;
            ofr[nd][2] *= corr_hi; ofr[nd][3] *= corr_hi;
        }
        __syncwarp();

        // --- O += P V : P via ldmatrix, V scalar (conflict-free pad 40) ---
        {
            const int rl = (lane >> 2);
            const int cl = (lane & 3);
            #pragma unroll
            for (int kk = 0; kk < 8; kk++) {
                uint32_t afr[4];
                LDSM_X4(afr, pldsm + (uint32_t)(kk * 32));
                #pragma unroll
                for (int nd = 0; nd < 4; nd++) {
                    uint32_t bfr[2];
                    bfr[0] = Vsu[(kk * 8 + cl) * 40 + nd * 8 + rl];
                    bfr[1] = Vsu[(kk * 8 + cl + 4) * 40 + nd * 8 + rl];
                    mma_tf32(ofr[nd], afr, bfr);
                }
            }
        }
        __syncwarp();
    }

    // final l reduction across quad + store (tf32-rounded for next GEMM)
    l_lo += __shfl_xor_sync(0xffffffffu, l_lo, 1);
    l_lo += __shfl_xor_sync(0xffffffffu, l_lo, 2);
    l_hi += __shfl_xor_sync(0xffffffffu, l_hi, 1);
    l_hi += __shfl_xor_sync(0xffffffffu, l_hi, 2);
    const float inv_lo = 1.0f / l_lo;
    const float inv_hi = 1.0f / l_hi;

    const int t_lo = qt * 128 + wid * 16 + (lane >> 2);
    const size_t ob_lo = (size_t)(b * TT + t_lo) * EE + h * HD + 2 * (lane & 3);
    const size_t ob_hi = ob_lo + 8 * EE;
    #pragma unroll
    for (int nd = 0; nd < 4; nd++) {
        float2 v0; v0.x = tf32_rn(ofr[nd][0] * inv_lo); v0.y = tf32_rn(ofr[nd][1] * inv_lo);
        float2 v1; v1.x = tf32_rn(ofr[nd][2] * inv_hi); v1.y = tf32_rn(ofr[nd][3] * inv_hi);
        *(float2*)&out[ob_lo + nd * 8] = v0;
        *(float2*)&out[ob_hi + nd * 8] = v1;
    }
}

// ---------------------------------------------------------------------------
// kernel_launch
// ---------------------------------------------------------------------------
extern "C" void kernel_launch(void* const* d_in, const int* in_sizes, int n_in,
                              void* d_out, int out_size) {
    const float* x     = (const float*)d_in[0];
    const float* qkv_w = (const float*)d_in[1];
    const float* qkv_b = (const float*)d_in[2];
    const float* out_w = (const float*)d_in[3];
    const float* out_b = (const float*)d_in[4];
    const float* ff1_w = (const float*)d_in[5];
    const float* ff1_b = (const float*)d_in[6];
    const float* ff2_w = (const float*)d_in[7];
    const float* ff2_b = (const float*)d_in[8];
    const float* ln1_g = (const float*)d_in[9];
    const float* ln1_b = (const float*)d_in[10];
    const float* ln2_g = (const float*)d_in[11];
    const float* ln2_b = (const float*)d_in[12];
    float* outp = (float*)d_out;

    float *gx, *gqkv, *gattn, *gffh, *wq, *wo, *w1, *w2;
    cudaGetSymbolAddress((void**)&gx,   g_x);
    cudaGetSymbolAddress((void**)&gqkv, g_qkv);
    cudaGetSymbolAddress((void**)&gattn,g_attn);
    cudaGetSymbolAddress((void**)&gffh, g_ffh);
    cudaGetSymbolAddress((void**)&wq,   g_qkvw_t);
    cudaGetSymbolAddress((void**)&wo,   g_outw_t);
    cudaGetSymbolAddress((void**)&w1,   g_ff1w_t);
    cudaGetSymbolAddress((void**)&w2,   g_ff2w_t);

    cudaFuncSetAttribute(gemm_tc_kernel, cudaFuncAttributeMaxDynamicSharedMemorySize, GSMEM_TOTAL);
    cudaFuncSetAttribute(gemm_ln_kernel, cudaFuncAttributeMaxDynamicSharedMemorySize, LSMEM_TOTAL);
    cudaFuncSetAttribute(attn_tc_kernel, cudaFuncAttributeMaxDynamicSharedMemorySize, ASMEM_TOTAL);

    // all weight transposes in one launch
    transpose_all_kernel<<<3072, dim3(32, 8)>>>(qkv_w, out_w, ff1_w, ff2_w, wq, wo, w1, w2);

    pe_kernel<<<(MROWS * EE + 255) / 256, 256>>>(x, gx);

    for (int i = 0; i < LL; i++) {
        // qkv = x @ qkv_w + b    (8192 x 768, K=256)  -> tf32-rounded output
        gemm_tc_kernel<<<dim3(6, 64), 256, GSMEM_TOTAL>>>(
            gx, wq + (size_t)i * 3 * EE * EE, qkv_b + (size_t)i * 3 * EE,
            gqkv, 3 * EE, EE, 2);

        // tensor-core flash attention (output tf32-rounded)
        attn_tc_kernel<<<dim3(TT / 128, BB * HH), 256, ASMEM_TOTAL>>>(gqkv, gattn);

        // x = LN(x + attn @ out_w + out_b)    (fused; full precision output)
        gemm_ln_kernel<<<MROWS / 64, 256, LSMEM_TOTAL>>>(
            gattn, wo + (size_t)i * EE * EE, out_b + (size_t)i * EE,
            gx, ln1_g + (size_t)i * EE, ln1_b + (size_t)i * EE, gx, EE);

        // h = relu(x @ ff1_w + b)  (8192 x 1024, K=256) -> relu + tf32-rounded
        gemm_tc_kernel<<<dim3(8, 64), 256, GSMEM_TOTAL>>>(
            gx, w1 + (size_t)i * FEE * EE * EE, ff1_b + (size_t)i * FEE * EE,
            gffh, FEE * EE, EE, 3);

        // x = LN(x + h @ ff2_w + ff2_b)       (fused; K=1024)
        float* dst = (i == LL - 1) ? outp : gx;
        gemm_ln_kernel<<<MROWS / 64, 256, LSMEM_TOTAL>>>(
            gffh, w2 + (size_t)i * FEE * EE * EE, ff2_b + (size_t)i * EE,
            gx, ln2_g + (size_t)i * EE, ln2_b + (size_t)i * EE, dst, FEE * EE);
    }
}

// round 14
// speedup vs baseline: 1.6344x; 1.6344x over previous
#include <cuda_runtime.h>
#include <cuda_bf16.h>
#include <math.h>
#include <cstdint>

// Problem constants
#define BB 4
#define TT 2048
#define EE 256
#define HH 8
#define HD 32
#define FEE 4
#define LL 4
#define MROWS (BB*TT)          // 8192
#define EPS 1e-5f

// ---------------------------------------------------------------------------
// Scratch (device globals; no runtime allocation allowed)
// ---------------------------------------------------------------------------
__device__ float g_x   [MROWS * EE];          // residual stream (full fp32)
__device__ float g_qkv [MROWS * 3 * EE];
__device__ float g_attn[MROWS * EE];
__device__ float g_ffh [MROWS * FEE * EE];
// transposed weights [N, K] row-major, per layer (tf32-rounded)
__device__ float g_qkvw_t[LL * 3 * EE * EE];
__device__ float g_outw_t[LL * EE * EE];
__device__ float g_ff1w_t[LL * FEE * EE * EE];
__device__ float g_ff2w_t[LL * FEE * EE * EE];

// ---------------------------------------------------------------------------
// PTX helpers (sm_80-era only; target is plain sm_103 — no tcgen05!)
// ---------------------------------------------------------------------------
__device__ __forceinline__ uint32_t smem_u32(const void* p) {
    uint32_t a;
    asm("{ .reg .u64 t; cvta.to.shared.u64 t, %1; cvt.u32.u64 %0, t; }" : "=r"(a) : "l"(p));
    return a;
}

__device__ __forceinline__ float tf32_rn(float x) {
    uint32_t u;
    asm("cvt.rna.tf32.f32 %0, %1;" : "=r"(u) : "f"(x));
    return __uint_as_float(u);
}

#define CP_ASYNC16(dst, src) \
    asm volatile("cp.async.cg.shared.global [%0], [%1], 16;\n" :: "r"(dst), "l"(src))
#define CP_COMMIT() asm volatile("cp.async.commit_group;\n" ::)
#define CP_WAIT1() asm volatile("cp.async.wait_group 1;\n" ::)
#define CP_WAIT0() asm volatile("cp.async.wait_group 0;\n" ::)

#define LDSM_X4(r, addr) \
    asm volatile("ldmatrix.sync.aligned.m8n8.x4.shared.b16 {%0,%1,%2,%3}, [%4];" \
        : "=r"((r)[0]), "=r"((r)[1]), "=r"((r)[2]), "=r"((r)[3]) : "r"(addr))

__device__ __forceinline__ void mma_tf32(float c[4], const uint32_t a[4], const uint32_t b[2]) {
    asm volatile("mma.sync.aligned.m16n8k8.row.col.f32.tf32.tf32.f32 "
        "{%0,%1,%2,%3}, {%4,%5,%6,%7}, {%8,%9}, {%0,%1,%2,%3};"
        : "+f"(c[0]), "+f"(c[1]), "+f"(c[2]), "+f"(c[3])
        : "r"(a[0]), "r"(a[1]), "r"(a[2]), "r"(a[3]), "r"(b[0]), "r"(b[1]));
}

// ---------------------------------------------------------------------------
// Positional encoding (full precision; GEMM rounds A in-register)
// ---------------------------------------------------------------------------
__global__ void pe_kernel(const float* __restrict__ x, float* __restrict__ out) {
    int idx = blockIdx.x * blockDim.x + threadIdx.x;
    if (idx >= MROWS * EE) return;
    int e = idx & (EE - 1);
    int t = (idx / EE) & (TT - 1);
    int i = (e < 128) ? e : e - 128;
    float f = __expf(-((2.0f * (float)i) * (1.0f / (float)EE)) * 9.210340371976184f);
    float ang = (float)t * f;
    float pe = (e < 128) ? sinf(ang) : cosf(ang);
    out[idx] = x[idx] + pe;
}

// ---------------------------------------------------------------------------
// Merged weight transpose + tf32 RN: all 4 weights, all layers, one launch.
// ---------------------------------------------------------------------------
__global__ void transpose_all_kernel(const float* __restrict__ qkv_w,
                                     const float* __restrict__ out_w,
                                     const float* __restrict__ ff1_w,
                                     const float* __restrict__ ff2_w,
                                     float* __restrict__ wq, float* __restrict__ wo,
                                     float* __restrict__ w1, float* __restrict__ w2) {
    __shared__ float tile[32][33];
    int id = blockIdx.x;
    const float* in; float* out; int K, N, ntiles;
    if (id < 768)        { in = qkv_w; out = wq; K = 256;  N = 768;  ntiles = 24; }
    else if (id < 1024)  { id -= 768;  in = out_w; out = wo; K = 256;  N = 256;  ntiles = 8; }
    else if (id < 2048)  { id -= 1024; in = ff1_w; out = w1; K = 256;  N = 1024; ntiles = 32; }
    else                 { id -= 2048; in = ff2_w; out = w2; K = 1024; N = 256;  ntiles = 8; }
    const int per_layer = ntiles * (K / 32);
    const int l = id / per_layer;
    const int r = id % per_layer;
    const int n0 = (r % ntiles) * 32;
    const int k0 = (r / ntiles) * 32;
    const size_t plane = (size_t)K * N;
    const float* ip = in + (size_t)l * plane;
    float* op = out + (size_t)l * plane;
    int tx = threadIdx.x, ty = threadIdx.y;
    #pragma unroll
    for (int i = 0; i < 32; i += 8)
        tile[ty + i][tx] = ip[(size_t)(k0 + ty + i) * N + n0 + tx];
    __syncthreads();
    #pragma unroll
    for (int i = 0; i < 32; i += 8)
        op[(size_t)(n0 + ty + i) * K + k0 + tx] = tf32_rn(tile[tx][ty + i]);
}

// ---------------------------------------------------------------------------
// tf32 mma.sync GEMM: C[M,N] = A[M,K] @ Bt[N,K]^T + bias
// mode bit0=ReLU, bit1=round out. 128x128 tile, BK=32, 3-stage cp.async.
// ---------------------------------------------------------------------------
#define GSTAGE 32768
#define GSMEM_TOTAL (3 * GSTAGE)

__device__ __forceinline__ void gemm_load_stage(uint32_t sbase, const float* A, const float* Bt,
                                                int K, int bm, int bn, int kt, int tid) {
    uint32_t abuf = sbase + (uint32_t)(kt % 3) * GSTAGE;
    uint32_t bbuf = abuf + 16384;
    const float* ap = A + (size_t)bm * K + kt * 32;
    const float* bp = Bt + (size_t)bn * K + kt * 32;
    #pragma unroll
    for (int i = 0; i < 4; i++) {
        int f = tid + i * 256;
        int r = f >> 3;
        int cB = (f & 7) * 16;
        uint32_t off = (uint32_t)(r * 128 + cB);
        uint32_t sw = off ^ ((off >> 3) & 0x70);
        CP_ASYNC16(abuf + sw, ap + (size_t)r * K + (cB >> 2));
        CP_ASYNC16(bbuf + sw, bp + (size_t)r * K + (cB >> 2));
    }
    CP_COMMIT();
}

__global__ __launch_bounds__(256)
void gemm_tc_kernel(const float* __restrict__ A, const float* __restrict__ Bt,
                    const float* __restrict__ bias, float* __restrict__ C,
                    int N, int K, int mode) {
    extern __shared__ char smem[];
    uint32_t sbase = smem_u32(smem);
    const int tid = threadIdx.x;
    const int wid = tid >> 5;
    const int lane = tid & 31;
    const int warpM = wid & 1;
    const int warpN = wid >> 1;
    const int bn = blockIdx.x * 128;
    const int bm = blockIdx.y * 128;

    float acc[4][4][4];
    #pragma unroll
    for (int mt = 0; mt < 4; mt++)
        #pragma unroll
        for (int nt = 0; nt < 4; nt++)
            #pragma unroll
            for (int r = 0; r < 4; r++) acc[mt][nt][r] = 0.0f;

    const uint32_t mask = (uint32_t)(lane & 7) << 4;
    uint32_t arowb[4];
    #pragma unroll
    for (int mt = 0; mt < 4; mt++)
        arowb[mt] = (uint32_t)(warpM * 64 + (lane & 15) + mt * 16) * 128;
    const uint32_t achunk = (uint32_t)(lane >> 4) * 16;
    uint32_t browb[2];
    #pragma unroll
    for (int nh = 0; nh < 2; nh++)
        browb[nh] = (uint32_t)(warpN * 32 + nh * 16 + (lane & 7) + ((lane >> 4) << 3)) * 128;
    const uint32_t bchunk = (uint32_t)((lane >> 3) & 1) * 16;

    const int nk = K / 32;
    gemm_load_stage(sbase, A, Bt, K, bm, bn, 0, tid);
    gemm_load_stage(sbase, A, Bt, K, bm, bn, 1, tid);

    for (int kt = 0; kt < nk; kt++) {
        if (kt + 1 < nk) { CP_WAIT1(); } else { CP_WAIT0(); }
        __syncthreads();
        if (kt + 2 < nk) gemm_load_stage(sbase, A, Bt, K, bm, bn, kt + 2, tid);

        const uint32_t ab = sbase + (uint32_t)(kt % 3) * GSTAGE;
        const uint32_t bb = ab + 16384;

        #pragma unroll
        for (int ks = 0; ks < 4; ks++) {
            const uint32_t aco = ((uint32_t)(ks * 32) + achunk) ^ mask;
            const uint32_t bco = ((uint32_t)(ks * 32) + bchunk) ^ mask;

            uint32_t afr[4][4], bfr[2][4];
            #pragma unroll
            for (int mt = 0; mt < 4; mt++) LDSM_X4(afr[mt], ab + arowb[mt] + aco);
            #pragma unroll
            for (int nh = 0; nh < 2; nh++) LDSM_X4(bfr[nh], bb + browb[nh] + bco);

            #pragma unroll
            for (int mt = 0; mt < 4; mt++)
                #pragma unroll
                for (int r = 0; r < 4; r++)
                    afr[mt][r] = __float_as_uint(tf32_rn(__uint_as_float(afr[mt][r])));

            #pragma unroll
            for (int mt = 0; mt < 4; mt++)
                #pragma unroll
                for (int nt = 0; nt < 4; nt++)
                    mma_tf32(acc[mt][nt], afr[mt], &bfr[nt >> 1][(nt & 1) * 2]);
        }
    }

    #pragma unroll
    for (int mt = 0; mt < 4; mt++) {
        const int row0 = bm + warpM * 64 + mt * 16 + (lane >> 2);
        #pragma unroll
        for (int nt = 0; nt < 4; nt++) {
            const int col = bn + warpN * 32 + nt * 8 + (lane & 3) * 2;
            const float2 bi = *(const float2*)&bias[col];
            float v0 = acc[mt][nt][0] + bi.x;
            float v1 = acc[mt][nt][1] + bi.y;
            float v2 = acc[mt][nt][2] + bi.x;
            float v3 = acc[mt][nt][3] + bi.y;
            if (mode & 1) {
                v0 = fmaxf(v0, 0.0f); v1 = fmaxf(v1, 0.0f);
                v2 = fmaxf(v2, 0.0f); v3 = fmaxf(v3, 0.0f);
            }
            if (mode & 2) {
                v0 = tf32_rn(v0); v1 = tf32_rn(v1);
                v2 = tf32_rn(v2); v3 = tf32_rn(v3);
            }
            float2 p0; p0.x = v0; p0.y = v1;
            float2 p1; p1.x = v2; p1.y = v3;
            *(float2*)&C[(size_t)row0 * N + col] = p0;
            *(float2*)&C[(size_t)(row0 + 8) * N + col] = p1;
        }
    }
}

// ---------------------------------------------------------------------------
// Fused GEMM (N=256) + bias + residual + LayerNorm (full-precision output)
// ---------------------------------------------------------------------------
#define LSTAGE 40960
#define LSMEM_TOTAL (3 * LSTAGE)

__device__ __forceinline__ void gemmln_load_stage(uint32_t sbase, const float* A, const float* Bt,
                                                  int K, int bm, int kt, int tid) {
    uint32_t abuf = sbase + (uint32_t)(kt % 3) * LSTAGE;
    uint32_t bbuf = abuf + 8192;
    const float* ap = A + (size_t)bm * K + kt * 32;
    const float* bp = Bt + kt * 32;
    #pragma unroll
    for (int i = 0; i < 2; i++) {
        int f = tid + i * 256;
        int r = f >> 3;
        int cB = (f & 7) * 16;
        uint32_t off = (uint32_t)(r * 128 + cB);
        uint32_t sw = off ^ ((off >> 3) & 0x70);
        CP_ASYNC16(abuf + sw, ap + (size_t)r * K + (cB >> 2));
    }
    #pragma unroll
    for (int i = 0; i < 8; i++) {
        int f = tid + i * 256;
        int r = f >> 3;
        int cB = (f & 7) * 16;
        uint32_t off = (uint32_t)(r * 128 + cB);
        uint32_t sw = off ^ ((off >> 3) & 0x70);
        CP_ASYNC16(bbuf + sw, bp + (size_t)r * K + (cB >> 2));
    }
    CP_COMMIT();
}

__global__ __launch_bounds__(256)
void gemm_ln_kernel(const float* __restrict__ A, const float* __restrict__ Bt,
                    const float* __restrict__ bias, const float* __restrict__ res,
                    const float* __restrict__ g, const float* __restrict__ beta,
                    float* __restrict__ out, int K) {
    extern __shared__ char smem[];
    uint32_t sbase = smem_u32(smem);
    const int tid = threadIdx.x;
    const int wid = tid >> 5;
    const int lane = tid & 31;
    const int warpM = wid & 1;
    const int warpN = wid >> 1;
    const int bm = blockIdx.x * 64;

    float acc[2][8][4];
    #pragma unroll
    for (int mt = 0; mt < 2; mt++)
        #pragma unroll
        for (int nt = 0; nt < 8; nt++)
            #pragma unroll
            for (int r = 0; r < 4; r++) acc[mt][nt][r] = 0.0f;

    const uint32_t mask = (uint32_t)(lane & 7) << 4;
    uint32_t arowb[2];
    #pragma unroll
    for (int mt = 0; mt < 2; mt++)
        arowb[mt] = (uint32_t)(warpM * 32 + mt * 16 + (lane & 15)) * 128;
    const uint32_t achunk = (uint32_t)(lane >> 4) * 16;
    uint32_t browb[4];
    #pragma unroll
    for (int nh = 0; nh < 4; nh++)
        browb[nh] = (uint32_t)(warpN * 64 + nh * 16 + (lane & 7) + ((lane >> 4) << 3)) * 128;
    const uint32_t bchunk = (uint32_t)((lane >> 3) & 1) * 16;

    const int nk = K / 32;
    gemmln_load_stage(sbase, A, Bt, K, bm, 0, tid);
    gemmln_load_stage(sbase, A, Bt, K, bm, 1, tid);

    for (int kt = 0; kt < nk; kt++) {
        if (kt + 1 < nk) { CP_WAIT1(); } else { CP_WAIT0(); }
        __syncthreads();
        if (kt + 2 < nk) gemmln_load_stage(sbase, A, Bt, K, bm, kt + 2, tid);

        const uint32_t ab = sbase + (uint32_t)(kt % 3) * LSTAGE;
        const uint32_t bb = ab + 8192;

        #pragma unroll
        for (int ks = 0; ks < 4; ks++) {
            const uint32_t aco = ((uint32_t)(ks * 32) + achunk) ^ mask;
            const uint32_t bco = ((uint32_t)(ks * 32) + bchunk) ^ mask;

            uint32_t afr[2][4], bfr[4][4];
            #pragma unroll
            for (int mt = 0; mt < 2; mt++) LDSM_X4(afr[mt], ab + arowb[mt] + aco);
            #pragma unroll
            for (int nh = 0; nh < 4; nh++) LDSM_X4(bfr[nh], bb + browb[nh] + bco);

            #pragma unroll
            for (int mt = 0; mt < 2; mt++)
                #pragma unroll
                for (int nt = 0; nt < 8; nt++)
                    mma_tf32(acc[mt][nt], afr[mt], &bfr[nt >> 1][(nt & 1) * 2]);
        }
    }
    __syncthreads();

    float* redS = (float*)smem;
    float* redQ = (float*)smem + 256;

    const int rl = lane >> 2;
    const int cl = (lane & 3) * 2;
    float sum[2][2] = {{0,0},{0,0}}, sq[2][2] = {{0,0},{0,0}};

    #pragma unroll
    for (int mt = 0; mt < 2; mt++) {
        const int rlo = bm + warpM * 32 + mt * 16 + rl;
        #pragma unroll
        for (int nt = 0; nt < 8; nt++) {
            const int col = warpN * 64 + nt * 8 + cl;
            const float2 bi = *(const float2*)&bias[col];
            const float2 r0 = *(const float2*)&res[(size_t)rlo * EE + col];
            const float2 r1 = *(const float2*)&res[(size_t)(rlo + 8) * EE + col];
            float v0 = acc[mt][nt][0] + bi.x + r0.x;
            float v1 = acc[mt][nt][1] + bi.y + r0.y;
            float v2 = acc[mt][nt][2] + bi.x + r1.x;
            float v3 = acc[mt][nt][3] + bi.y + r1.y;
            acc[mt][nt][0] = v0; acc[mt][nt][1] = v1;
            acc[mt][nt][2] = v2; acc[mt][nt][3] = v3;
            sum[mt][0] += v0 + v1;     sum[mt][1] += v2 + v3;
            sq[mt][0]  += v0*v0 + v1*v1; sq[mt][1] += v2*v2 + v3*v3;
        }
    }
    #pragma unroll
    for (int mt = 0; mt < 2; mt++)
        #pragma unroll
        for (int hh = 0; hh < 2; hh++) {
            sum[mt][hh] += __shfl_xor_sync(0xffffffffu, sum[mt][hh], 1);
            sum[mt][hh] += __shfl_xor_sync(0xffffffffu, sum[mt][hh], 2);
            sq[mt][hh]  += __shfl_xor_sync(0xffffffffu, sq[mt][hh], 1);
            sq[mt][hh]  += __shfl_xor_sync(0xffffffffu, sq[mt][hh], 2);
        }
    if ((lane & 3) == 0) {
        #pragma unroll
        for (int mt = 0; mt < 2; mt++) {
            int rloc = warpM * 32 + mt * 16 + rl;
            redS[rloc * 4 + warpN] = sum[mt][0];
            redQ[rloc * 4 + warpN] = sq[mt][0];
            redS[(rloc + 8) * 4 + warpN] = sum[mt][1];
            redQ[(rloc + 8) * 4 + warpN] = sq[mt][1];
        }
    }
    __syncthreads();

    #pragma unroll
    for (int mt = 0; mt < 2; mt++) {
        #pragma unroll
        for (int hh = 0; hh < 2; hh++) {
            const int rloc = warpM * 32 + mt * 16 + rl + hh * 8;
            float ts = redS[rloc * 4 + 0] + redS[rloc * 4 + 1]
                     + redS[rloc * 4 + 2] + redS[rloc * 4 + 3];
            float tq = redQ[rloc * 4 + 0] + redQ[rloc * 4 + 1]
                     + redQ[rloc * 4 + 2] + redQ[rloc * 4 + 3];
            const float mu = ts * (1.0f / (float)EE);
            const float var = tq * (1.0f / (float)EE) - mu * mu;
            const float inv = rsqrtf(var + EPS);
            const int row = bm + rloc;
            #pragma unroll
            for (int nt = 0; nt < 8; nt++) {
                const int col = warpN * 64 + nt * 8 + cl;
                const float2 gg = *(const float2*)&g[col];
                const float2 bb = *(const float2*)&beta[col];
                float v0 = acc[mt][nt][2 * hh + 0];
                float v1 = acc[mt][nt][2 * hh + 1];
                float2 o;
                o.x = (v0 - mu) * inv * gg.x + bb.x;
                o.y = (v1 - mu) * inv * gg.y + bb.y;
                *(float2*)&out[(size_t)row * EE + col] = o;
            }
        }
    }
}

// ---------------------------------------------------------------------------
// Tensor-core flash attention, v2: 4 warps x 32 query rows (2 m16-tiles/warp).
// KV tiles of 64 keys (2-stage cp.async), processed in two 32-key halves.
// K fragments and V values are SHARED across both m-tiles (halves smem reads).
// smem: 2*18432 (KV) + 4*4608 (P) = 55296 -> 3 CTAs/SM.
// ---------------------------------------------------------------------------
#define AST_K 8192                      // 64 keys x 128B (swizzled)
#define AST_V 10240                     // 64 keys x 40 floats
#define ASTAGE (AST_K + AST_V)          // 18432
#define APOFF (2 * ASTAGE)              // 36864
#define PWARP (32 * 36 * 4)             // 4608 bytes per warp (32 rows x 36 floats)
#define ASMEM_TOTAL (APOFF + 4 * PWARP) // 55296

__device__ __forceinline__ void attn_load_kv(uint32_t sbase, const float* kv0,
                                             int kt, int tid) {
    uint32_t kbuf = sbase + (uint32_t)(kt & 1) * ASTAGE;
    uint32_t vbuf = kbuf + AST_K;
    const float* src0 = kv0 + (size_t)(kt * 64) * 768;
    #pragma unroll
    for (int i = 0; i < 4; i++) {
        int f = tid + i * 128;           // 0..511
        int j = f >> 3;                  // key 0..63
        int c = f & 7;                   // 16B chunk
        const float* s = src0 + (size_t)j * 768 + 32 + c * 4;   // K slot
        uint32_t koff = (uint32_t)(j * 128 + c * 16);
        CP_ASYNC16(kbuf + (koff ^ ((koff >> 3) & 0x70)), s);
        CP_ASYNC16(vbuf + (uint32_t)(j * 160 + c * 16), s + 32); // V slot
    }
    CP_COMMIT();
}

__global__ __launch_bounds__(128, 3)
void attn_tc_kernel(const float* __restrict__ qkv, float* __restrict__ out) {
    extern __shared__ char smem[];
    uint32_t sbase = smem_u32(smem);

    const int tid = threadIdx.x;
    const int wid = tid >> 5;                // 0..3
    const int lane = tid & 31;
    const int qt = blockIdx.x;               // 0..15 (128 queries each)
    const int bh = blockIdx.y;               // 0..31
    const int h = bh & (HH - 1);
    const int b = bh >> 3;

    const float scale = 0.2550348612890183f;   // 1/sqrt(32) * log2(e)

    // --- Q fragments for 2 m-tiles ---
    uint32_t qfr[2][4][4];
    #pragma unroll
    for (int mt = 0; mt < 2; mt++) {
        const int r_lo = qt * 128 + wid * 32 + mt * 16 + (lane >> 2);
        const size_t base_lo = (size_t)(b * TT + r_lo) * 768 + h * 96;
        const size_t base_hi = base_lo + 8 * 768;
        #pragma unroll
        for (int ks = 0; ks < 4; ks++) {
            int c0 = ks * 8 + (lane & 3);
            qfr[mt][ks][0] = __float_as_uint(tf32_rn(qkv[base_lo + c0] * scale));
            qfr[mt][ks][1] = __float_as_uint(tf32_rn(qkv[base_hi + c0] * scale));
            qfr[mt][ks][2] = __float_as_uint(tf32_rn(qkv[base_lo + c0 + 4] * scale));
            qfr[mt][ks][3] = __float_as_uint(tf32_rn(qkv[base_hi + c0 + 4] * scale));
        }
    }

    float ofr[2][4][4];
    #pragma unroll
    for (int mt = 0; mt < 2; mt++)
        #pragma unroll
        for (int nd = 0; nd < 4; nd++)
            #pragma unroll
            for (int r = 0; r < 4; r++) ofr[mt][nd][r] = 0.0f;
    float m_lo[2] = {-INFINITY, -INFINITY}, m_hi[2] = {-INFINITY, -INFINITY};
    float l_lo[2] = {0.0f, 0.0f}, l_hi[2] = {0.0f, 0.0f};

    // K ldmatrix addressing (B fragments)
    const uint32_t mask = (uint32_t)(lane & 7) << 4;
    const uint32_t krow = (uint32_t)((lane & 7) + ((lane >> 4) << 3)) * 128;
    const uint32_t kchunk = (uint32_t)((lane >> 3) & 1) * 16;

    // P buffer: per warp, 32 rows (mt0: 0..15, mt1: 16..31) x 36 floats
    float* Pw = (float*)(smem + APOFF + wid * PWARP);
    const uint32_t pbase = sbase + APOFF + (uint32_t)(wid * PWARP);
    const uint32_t pldsm0 = pbase + (uint32_t)((lane & 15) * 144) + ((uint32_t)(lane >> 4) << 4);
    const uint32_t pldsm1 = pldsm0 + 16 * 144;

    const float* kv0 = qkv + (size_t)(b * TT) * 768 + h * 96;

    attn_load_kv(sbase, kv0, 0, tid);

    const int nk = TT / 64;
    for (int kt = 0; kt < nk; kt++) {
        CP_WAIT0();
        __syncthreads();
        if (kt + 1 < nk) attn_load_kv(sbase, kv0, kt + 1, tid);

        const uint32_t kb = sbase + (uint32_t)(kt & 1) * ASTAGE;
        const uint32_t* Vsu = (const uint32_t*)(smem + (kt & 1) * ASTAGE + AST_K);

        #pragma unroll
        for (int half = 0; half < 2; half++) {
            // --- S = Q K^T for 32 keys (shared K fragments across m-tiles) ---
            float sfr[2][4][4];
            #pragma unroll
            for (int mt = 0; mt < 2; mt++)
                #pragma unroll
                for (int nt = 0; nt < 4; nt++)
                    #pragma unroll
                    for (int r = 0; r < 4; r++) sfr[mt][nt][r] = 0.0f;

            #pragma unroll
            for (int ks = 0; ks < 4; ks++) {
                const uint32_t co = ((uint32_t)(ks * 32) + kchunk) ^ mask;
                uint32_t kfr[2][4];
                LDSM_X4(kfr[0], kb + (uint32_t)((half * 2 + 0) * 2048) + krow + co);
                LDSM_X4(kfr[1], kb + (uint32_t)((half * 2 + 1) * 2048) + krow + co);
                #pragma unroll
                for (int mt = 0; mt < 2; mt++)
                    #pragma unroll
                    for (int nt = 0; nt < 4; nt++)
                        mma_tf32(sfr[mt][nt], qfr[mt][ks], &kfr[nt >> 1][(nt & 1) * 2]);
            }

            // --- online softmax per m-tile (log2 domain) ---
            #pragma unroll
            for (int mt = 0; mt < 2; mt++) {
                float mx_lo = sfr[mt][0][0], mx_hi = sfr[mt][0][2];
                #pragma unroll
                for (int nt = 0; nt < 4; nt++) {
                    mx_lo = fmaxf(mx_lo, fmaxf(sfr[mt][nt][0], sfr[mt][nt][1]));
                    mx_hi = fmaxf(mx_hi, fmaxf(sfr[mt][nt][2], sfr[mt][nt][3]));
                }
                mx_lo = fmaxf(mx_lo, __shfl_xor_sync(0xffffffffu, mx_lo, 1));
                mx_lo = fmaxf(mx_lo, __shfl_xor_sync(0xffffffffu, mx_lo, 2));
                mx_hi = fmaxf(mx_hi, __shfl_xor_sync(0xffffffffu, mx_hi, 1));
                mx_hi = fmaxf(mx_hi, __shfl_xor_sync(0xffffffffu, mx_hi, 2));

                const float nm_lo = fmaxf(m_lo[mt], mx_lo);
                const float nm_hi = fmaxf(m_hi[mt], mx_hi);
                const float corr_lo = exp2f(m_lo[mt] - nm_lo);  // 2^-inf = 0 first tile
                const float corr_hi = exp2f(m_hi[mt] - nm_hi);
                m_lo[mt] = nm_lo; m_hi[mt] = nm_hi;

                float ps_lo = 0.0f, ps_hi = 0.0f;
                {
                    const int rl = (lane >> 2);
                    const int cb = 2 * (lane & 3);
                    float* prow_lo = Pw + (mt * 16 + rl) * 36 + cb;
                    float* prow_hi = Pw + (mt * 16 + rl + 8) * 36 + cb;
                    #pragma unroll
                    for (int nt = 0; nt < 4; nt++) {
                        float p0 = exp2f(sfr[mt][nt][0] - nm_lo);
                        float p1 = exp2f(sfr[mt][nt][1] - nm_lo);
                        float p2 = exp2f(sfr[mt][nt][2] - nm_hi);
                        float p3 = exp2f(sfr[mt][nt][3] - nm_hi);
                        ps_lo += p0 + p1;
                        ps_hi += p2 + p3;
                        float2 w0; w0.x = tf32_rn(p0); w0.y = tf32_rn(p1);
                        float2 w1; w1.x = tf32_rn(p2); w1.y = tf32_rn(p3);
                        *(float2*)(prow_lo + nt * 8) = w0;
                        *(float2*)(prow_hi + nt * 8) = w1;
                    }
                }
                l_lo[mt] = l_lo[mt] * corr_lo + ps_lo;
                l_hi[mt] = l_hi[mt] * corr_hi + ps_hi;
                #pragma unroll
                for (int nd = 0; nd < 4; nd++) {
                    ofr[mt][nd][0] *= corr_lo; ofr[mt][nd][1] *= corr_lo;
                    ofr[mt][nd][2] *= corr_hi; ofr[mt][nd][3] *= corr_hi;
                }
            }
            __syncwarp();

            // --- O += P V : V values shared across both m-tiles ---
            {
                const int rl = (lane >> 2);
                const int cl = (lane & 3);
                #pragma unroll
                for (int kk = 0; kk < 4; kk++) {
                    uint32_t afr0[4], afr1[4];
                    LDSM_X4(afr0, pldsm0 + (uint32_t)(kk * 32));
                    LDSM_X4(afr1, pldsm1 + (uint32_t)(kk * 32));
                    const int kbase = half * 32 + kk * 8;
                    #pragma unroll
                    for (int nd = 0; nd < 4; nd++) {
                        uint32_t bfr[2];
                        bfr[0] = Vsu[(kbase + cl) * 40 + nd * 8 + rl];
                        bfr[1] = Vsu[(kbase + cl + 4) * 40 + nd * 8 + rl];
                        mma_tf32(ofr[0][nd], afr0, bfr);
                        mma_tf32(ofr[1][nd], afr1, bfr);
                    }
                }
            }
            __syncwarp();   // P reused by next half
        }
    }

    // --- epilogue: l reduce + store (tf32-rounded for next GEMM) ---
    #pragma unroll
    for (int mt = 0; mt < 2; mt++) {
        float ll = l_lo[mt], lh = l_hi[mt];
        ll += __shfl_xor_sync(0xffffffffu, ll, 1);
        ll += __shfl_xor_sync(0xffffffffu, ll, 2);
        lh += __shfl_xor_sync(0xffffffffu, lh, 1);
        lh += __shfl_xor_sync(0xffffffffu, lh, 2);
        const float inv_lo = 1.0f / ll;
        const float inv_hi = 1.0f / lh;

        const int t_lo = qt * 128 + wid * 32 + mt * 16 + (lane >> 2);
        const size_t ob_lo = (size_t)(b * TT + t_lo) * EE + h * HD + 2 * (lane & 3);
        const size_t ob_hi = ob_lo + 8 * EE;
        #pragma unroll
        for (int nd = 0; nd < 4; nd++) {
            float2 v0; v0.x = tf32_rn(ofr[mt][nd][0] * inv_lo); v0.y = tf32_rn(ofr[mt][nd][1] * inv_lo);
            float2 v1; v1.x = tf32_rn(ofr[mt][nd][2] * inv_hi); v1.y = tf32_rn(ofr[mt][nd][3] * inv_hi);
            *(float2*)&out[ob_lo + nd * 8] = v0;
            *(float2*)&out[ob_hi + nd * 8] = v1;
        }
    }
}

// ---------------------------------------------------------------------------
// kernel_launch
// ---------------------------------------------------------------------------
extern "C" void kernel_launch(void* const* d_in, const int* in_sizes, int n_in,
                              void* d_out, int out_size) {
    const float* x     = (const float*)d_in[0];
    const float* qkv_w = (const float*)d_in[1];
    const float* qkv_b = (const float*)d_in[2];
    const float* out_w = (const float*)d_in[3];
    const float* out_b = (const float*)d_in[4];
    const float* ff1_w = (const float*)d_in[5];
    const float* ff1_b = (const float*)d_in[6];
    const float* ff2_w = (const float*)d_in[7];
    const float* ff2_b = (const float*)d_in[8];
    const float* ln1_g = (const float*)d_in[9];
    const float* ln1_b = (const float*)d_in[10];
    const float* ln2_g = (const float*)d_in[11];
    const float* ln2_b = (const float*)d_in[12];
    float* outp = (float*)d_out;

    float *gx, *gqkv, *gattn, *gffh, *wq, *wo, *w1, *w2;
    cudaGetSymbolAddress((void**)&gx,   g_x);
    cudaGetSymbolAddress((void**)&gqkv, g_qkv);
    cudaGetSymbolAddress((void**)&gattn,g_attn);
    cudaGetSymbolAddress((void**)&gffh, g_ffh);
    cudaGetSymbolAddress((void**)&wq,   g_qkvw_t);
    cudaGetSymbolAddress((void**)&wo,   g_outw_t);
    cudaGetSymbolAddress((void**)&w1,   g_ff1w_t);
    cudaGetSymbolAddress((void**)&w2,   g_ff2w_t);

    cudaFuncSetAttribute(gemm_tc_kernel, cudaFuncAttributeMaxDynamicSharedMemorySize, GSMEM_TOTAL);
    cudaFuncSetAttribute(gemm_ln_kernel, cudaFuncAttributeMaxDynamicSharedMemorySize, LSMEM_TOTAL);
    cudaFuncSetAttribute(attn_tc_kernel, cudaFuncAttributeMaxDynamicSharedMemorySize, ASMEM_TOTAL);

    transpose_all_kernel<<<3072, dim3(32, 8)>>>(qkv_w, out_w, ff1_w, ff2_w, wq, wo, w1, w2);

    pe_kernel<<<(MROWS * EE + 255) / 256, 256>>>(x, gx);

    for (int i = 0; i < LL; i++) {
        // qkv = x @ qkv_w + b  -> tf32-rounded output
        gemm_tc_kernel<<<dim3(6, 64), 256, GSMEM_TOTAL>>>(
            gx, wq + (size_t)i * 3 * EE * EE, qkv_b + (size_t)i * 3 * EE,
            gqkv, 3 * EE, EE, 2);

        // flash attention (4 warps, 128 queries, 3 CTA/SM)
        attn_tc_kernel<<<dim3(TT / 128, BB * HH), 128, ASMEM_TOTAL>>>(gqkv, gattn);

        // x = LN(x + attn @ out_w + out_b)
        gemm_ln_kernel<<<MROWS / 64, 256, LSMEM_TOTAL>>>(
            gattn, wo + (size_t)i * EE * EE, out_b + (size_t)i * EE,
            gx, ln1_g + (size_t)i * EE, ln1_b + (size_t)i * EE, gx, EE);

        // h = relu(x @ ff1_w + b) -> relu + tf32-rounded
        gemm_tc_kernel<<<dim3(8, 64), 256, GSMEM_TOTAL>>>(
            gx, w1 + (size_t)i * FEE * EE * EE, ff1_b + (size_t)i * FEE * EE,
            gffh, FEE * EE, EE, 3);

        // x = LN(x + h @ ff2_w + ff2_b)
        float* dst = (i == LL - 1) ? outp : gx;
        gemm_ln_kernel<<<MROWS / 64, 256, LSMEM_TOTAL>>>(
            gffh, w2 + (size_t)i * FEE * EE * EE, ff2_b + (size_t)i * EE,
            gx, ln2_g + (size_t)i * EE, ln2_b + (size_t)i * EE, dst, FEE * EE);
    }
}